// round 1
// baseline (speedup 1.0000x reference)
#include <cuda_runtime.h>
#include <math.h>

#define N      8192
#define FIN    256
#define FOUT   64
#define TPB    256
#define JPT    (N / TPB / 4)   // float4 iterations per thread in k_attn = 8
#define CAP    2048            // neighbor-list capacity (expected ~32, max ~70)
#define LBUF   10              // per-thread local neighbor buffer
#define NEGTH  (-1e8f)         // adj == 0 (neighbor) vs -1e9 (not)
#define LRELU_ALPHA 0.2f

// ---------------- scratch (static __device__, allocation-free) --------------
__device__ __align__(16) static float g_fts[N * FOUT];
__device__ __align__(16) static float g_f1[N];
__device__ __align__(16) static float g_f2[N];

// ---------------- kernel 1: fts = x @ W  (8 rows per 64-thread block) -------
#define ROWS1 8
__global__ void k_proj(const float* __restrict__ x, const float* __restrict__ W) {
    __shared__ float xs[ROWS1 * FIN];
    const int f    = threadIdx.x;          // 0..63  (output feature)
    const int row0 = blockIdx.x * ROWS1;

    for (int i = threadIdx.x; i < ROWS1 * FIN; i += blockDim.x)
        xs[i] = x[row0 * FIN + i];
    __syncthreads();

    float acc[ROWS1];
#pragma unroll
    for (int r = 0; r < ROWS1; r++) acc[r] = 0.f;

#pragma unroll 4
    for (int k = 0; k < FIN; k++) {
        const float w = __ldg(&W[k * FOUT + f]);   // 64KB, L1-resident
#pragma unroll
        for (int r = 0; r < ROWS1; r++)
            acc[r] = fmaf(xs[r * FIN + k], w, acc[r]);
    }
#pragma unroll
    for (int r = 0; r < ROWS1; r++)
        g_fts[(row0 + r) * FOUT + f] = acc[r];
}

// ---------------- kernel 2: f1/f2 = fts @ a1/a2 + b  (warp per row) ---------
__global__ void k_f12(const float* __restrict__ a1, const float* __restrict__ a2,
                      const float* __restrict__ b1p, const float* __restrict__ b2p) {
    const int gw   = (blockIdx.x * blockDim.x + threadIdx.x) >> 5;  // row
    const int lane = threadIdx.x & 31;
    if (gw >= N) return;
    const float v0 = g_fts[gw * FOUT + lane];
    const float v1 = g_fts[gw * FOUT + 32 + lane];
    float s1 = v0 * __ldg(&a1[lane]) + v1 * __ldg(&a1[32 + lane]);
    float s2 = v0 * __ldg(&a2[lane]) + v1 * __ldg(&a2[32 + lane]);
#pragma unroll
    for (int o = 16; o > 0; o >>= 1) {
        s1 += __shfl_down_sync(0xffffffffu, s1, o);
        s2 += __shfl_down_sync(0xffffffffu, s2, o);
    }
    if (lane == 0) {
        g_f1[gw] = s1 + b1p[0];
        g_f2[gw] = s2 + b2p[0];
    }
}

// ---------------- kernel 3: fused lrelu+adj -> softmax -> SpMM -> elu -------
__device__ __forceinline__ float lrelu(float v) {
    return v > 0.f ? v : LRELU_ALPHA * v;
}

__global__ __launch_bounds__(TPB) void k_attn(const float* __restrict__ adj,
                                              const float* __restrict__ bias,
                                              float* __restrict__ out) {
    const int row = blockIdx.x;
    const int tid = threadIdx.x;

    __shared__ int   s_idx[CAP];
    __shared__ float s_sc[CAP];
    __shared__ int   s_cnt[TPB];
    __shared__ float s_red[TPB / 32];
    __shared__ float s_m, s_S;
    __shared__ int   s_total;

    const float4* __restrict__ adjr = (const float4*)(adj + (size_t)row * N);
    const float4* __restrict__ f2v  = (const float4*)g_f2;
    const float f1i = g_f1[row];

    // ---- pass 1: streaming scan of adj row; local max + neighbor gather ----
    float lmax = -INFINITY;
    int   lj[LBUF];
    float ls[LBUF];
    int   lcnt = 0;

#pragma unroll
    for (int it = 0; it < JPT; it++) {
        const int c  = it * TPB + tid;      // float4 index (coalesced)
        const float4 a = adjr[c];
        const float4 f = f2v[c];
        const int j0 = c * 4;

        float s;
        s = lrelu(f1i + f.x) + a.x; lmax = fmaxf(lmax, s);
        if (a.x > NEGTH) { if (lcnt < LBUF) { lj[lcnt] = j0;     ls[lcnt] = s; } lcnt++; }
        s = lrelu(f1i + f.y) + a.y; lmax = fmaxf(lmax, s);
        if (a.y > NEGTH) { if (lcnt < LBUF) { lj[lcnt] = j0 + 1; ls[lcnt] = s; } lcnt++; }
        s = lrelu(f1i + f.z) + a.z; lmax = fmaxf(lmax, s);
        if (a.z > NEGTH) { if (lcnt < LBUF) { lj[lcnt] = j0 + 2; ls[lcnt] = s; } lcnt++; }
        s = lrelu(f1i + f.w) + a.w; lmax = fmaxf(lmax, s);
        if (a.w > NEGTH) { if (lcnt < LBUF) { lj[lcnt] = j0 + 3; ls[lcnt] = s; } lcnt++; }
    }

    // ---- block max reduction ----
#pragma unroll
    for (int o = 16; o > 0; o >>= 1)
        lmax = fmaxf(lmax, __shfl_xor_sync(0xffffffffu, lmax, o));
    if ((tid & 31) == 0) s_red[tid >> 5] = lmax;
    __syncthreads();
    if (tid == 0) {
        float m = s_red[0];
#pragma unroll
        for (int w = 1; w < TPB / 32; w++) m = fmaxf(m, s_red[w]);
        s_m = m;
    }

    // ---- deterministic compaction: prefix scan of per-thread counts ----
    const int lcnt_clamped = lcnt;
    s_cnt[tid] = lcnt_clamped;
    __syncthreads();
    for (int off = 1; off < TPB; off <<= 1) {
        int v = (tid >= off) ? s_cnt[tid - off] : 0;
        __syncthreads();
        s_cnt[tid] += v;
        __syncthreads();
    }
    const int total = s_cnt[TPB - 1];
    const int myoff = s_cnt[tid] - lcnt_clamped;   // exclusive prefix
    if (tid == 0) s_total = total;

    const bool fallback = (total > CAP) || (total == 0) || (lcnt > LBUF);
    // or-reduce overflow via shared flag
    __shared__ int s_fb;
    if (tid == 0) s_fb = 0;
    __syncthreads();
    if (fallback) s_fb = 1;
    if (!fallback && total <= CAP) {
        const int nwr = lcnt < LBUF ? lcnt : LBUF;
        for (int e = 0; e < nwr; e++) {
            s_idx[myoff + e] = lj[e];
            s_sc[myoff + e]  = ls[e];
        }
    }
    __syncthreads();
    const float m = s_m;

    if (s_fb == 0) {
        // ---- normal path: exp + sum over neighbor list ----
        float lsum = 0.f;
        for (int e = tid; e < s_total; e += TPB) {
            const float w = expf(s_sc[e] - m);
            s_sc[e] = w;
            lsum += w;
        }
#pragma unroll
        for (int o = 16; o > 0; o >>= 1)
            lsum += __shfl_xor_sync(0xffffffffu, lsum, o);
        if ((tid & 31) == 0) s_red[tid >> 5] = lsum;
        __syncthreads();
        if (tid == 0) {
            float S = 0.f;
#pragma unroll
            for (int w = 0; w < TPB / 32; w++) S += s_red[w];
            s_S = S;
        }
        __syncthreads();

        if (tid < FOUT) {
            const float invS = 1.0f / s_S;
            float acc = 0.f;
            const int tot = s_total;
            for (int e = 0; e < tot; e++)
                acc = fmaf(s_sc[e], g_fts[(size_t)s_idx[e] * FOUT + tid], acc);
            float v = acc * invS + __ldg(&bias[tid]);
            out[(size_t)row * FOUT + tid] = v > 0.f ? v : expm1f(v);
        }
    } else {
        // ---- fallback (never expected): streaming recompute, exact ----
        const float* __restrict__ adjs = adj + (size_t)row * N;
        float lsum = 0.f;
        for (int j = tid; j < N; j += TPB)
            lsum += expf(lrelu(f1i + g_f2[j]) + adjs[j] - m);
#pragma unroll
        for (int o = 16; o > 0; o >>= 1)
            lsum += __shfl_xor_sync(0xffffffffu, lsum, o);
        if ((tid & 31) == 0) s_red[tid >> 5] = lsum;
        __syncthreads();
        if (tid == 0) {
            float S = 0.f;
#pragma unroll
            for (int w = 0; w < TPB / 32; w++) S += s_red[w];
            s_S = S;
        }
        __syncthreads();

        if (tid < FOUT) {
            const float invS = 1.0f / s_S;
            float acc = 0.f;
            for (int j = 0; j < N; j++) {
                const float w = expf(lrelu(f1i + g_f2[j]) + adjs[j] - m);
                if (w > 0.f)
                    acc = fmaf(w, g_fts[(size_t)j * FOUT + tid], acc);
            }
            float v = acc * invS + __ldg(&bias[tid]);
            out[(size_t)row * FOUT + tid] = v > 0.f ? v : expm1f(v);
        }
    }
}

// ---------------- launcher ---------------------------------------------------
extern "C" void kernel_launch(void* const* d_in, const int* in_sizes, int n_in,
                              void* d_out, int out_size) {
    const float* x    = (const float*)d_in[0];  // [1, N, FIN]
    const float* adj  = (const float*)d_in[1];  // [1, N, N]
    const float* W    = (const float*)d_in[2];  // [FIN, FOUT]
    const float* a1   = (const float*)d_in[3];  // [FOUT, 1]
    const float* b1   = (const float*)d_in[4];  // [1]
    const float* a2   = (const float*)d_in[5];  // [FOUT, 1]
    const float* b2   = (const float*)d_in[6];  // [1]
    const float* bias = (const float*)d_in[7];  // [FOUT]
    float* out = (float*)d_out;                  // [1, N, FOUT]

    k_proj<<<N / ROWS1, FOUT>>>(x, W);
    k_f12<<<(N * 32) / 256, 256>>>(a1, a2, b1, b2);
    k_attn<<<N, TPB>>>(adj, bias, out);
}

// round 2
// speedup vs baseline: 1.5741x; 1.5741x over previous
#include <cuda_runtime.h>
#include <math.h>

#define N      8192
#define FIN    256
#define FOUT   64
#define NEGTH  (-1e8f)      // adj: 0.0f for neighbor, -1e9 otherwise
#define ALPHA  0.2f

// ---------------- scratch (static __device__, allocation-free) --------------
__device__ __align__(16) static float g_fts[N * FOUT];
__device__ __align__(16) static float g_f1[N];
__device__ __align__(16) static float g_f2[N];

// ============================================================================
// kernel 1: fts = x @ W  (+ fused f1/f2 = fts@a1+b1, fts@a2+b2)
// 32 rows x 64 fout per 128-thread block; 4x4 register micro-tile per thread.
// ============================================================================
#define TR  32
#define KC  32
__global__ __launch_bounds__(128) void k_proj(
        const float* __restrict__ x,  const float* __restrict__ W,
        const float* __restrict__ a1, const float* __restrict__ b1,
        const float* __restrict__ a2, const float* __restrict__ b2) {
    __shared__ float xs[KC][36];        // [k][row], pad->36 keeps float4 align
    __shared__ float ws[KC * FOUT];     // [k][f]

    const int tid  = threadIdx.x;
    const int row0 = blockIdx.x * TR;
    const int fg   = tid & 15;          // 16 f-groups
    const int rg   = tid >> 4;          // 8 row-groups
    const int f0   = fg * 4;
    const int r0   = rg * 4;
    const int lane = tid & 31;

    float acc[4][4] = {};

    for (int kc = 0; kc < FIN; kc += KC) {
        __syncthreads();
        // x tile, transposed into xs[k][r]  (coalesced global reads)
        {
            const int k  = tid & 31;
            const int rb = tid >> 5;
#pragma unroll
            for (int i = 0; i < 8; i++) {
                const int r = rb + i * 4;
                xs[k][r] = x[(size_t)(row0 + r) * FIN + kc + k];
            }
        }
        // W tile, straight copy (row-major matches)
        {
            const float4* W4  = (const float4*)(W + (size_t)kc * FOUT);
            float4*       ws4 = (float4*)ws;
#pragma unroll
            for (int i = 0; i < 4; i++)
                ws4[tid + i * 128] = W4[tid + i * 128];
        }
        __syncthreads();

#pragma unroll
        for (int k = 0; k < KC; k++) {
            const float4 xv = *(const float4*)&xs[k][r0];
            const float4 wv = *(const float4*)&ws[k * FOUT + f0];
            const float xr[4] = {xv.x, xv.y, xv.z, xv.w};
            const float wf[4] = {wv.x, wv.y, wv.z, wv.w};
#pragma unroll
            for (int r = 0; r < 4; r++)
#pragma unroll
                for (int j = 0; j < 4; j++)
                    acc[r][j] = fmaf(xr[r], wf[j], acc[r][j]);
        }
    }

    // store fts (float4, contiguous in f)
#pragma unroll
    for (int r = 0; r < 4; r++) {
        float4 v = make_float4(acc[r][0], acc[r][1], acc[r][2], acc[r][3]);
        *(float4*)&g_fts[(size_t)(row0 + r0 + r) * FOUT + f0] = v;
    }

    // fused f1/f2: per-thread partial over its 4 f's, then reduce across fg
    const float4 a1v = *(const float4*)&a1[f0];
    const float4 a2v = *(const float4*)&a2[f0];
    float p1[4], p2[4];
#pragma unroll
    for (int r = 0; r < 4; r++) {
        p1[r] = acc[r][0]*a1v.x + acc[r][1]*a1v.y + acc[r][2]*a1v.z + acc[r][3]*a1v.w;
        p2[r] = acc[r][0]*a2v.x + acc[r][1]*a2v.y + acc[r][2]*a2v.z + acc[r][3]*a2v.w;
    }
#pragma unroll
    for (int o = 1; o < 16; o <<= 1) {
#pragma unroll
        for (int r = 0; r < 4; r++) {
            p1[r] += __shfl_xor_sync(0xffffffffu, p1[r], o);
            p2[r] += __shfl_xor_sync(0xffffffffu, p2[r], o);
        }
    }
    if (fg == 0) {
        const float bb1 = __ldg(b1), bb2 = __ldg(b2);
#pragma unroll
        for (int r = 0; r < 4; r++) {
            g_f1[row0 + r0 + r] = p1[r] + bb1;
            g_f2[row0 + r0 + r] = p2[r] + bb2;
        }
    }
    (void)lane;
}

// ============================================================================
// kernel 2: fused sparse softmax + SpMM + elu. One block per row.
// Pass 1 just finds neighbor indices (adj > -1e8); scores computed only for
// neighbors (row max == neighbor max; non-neighbor exp == 0 exactly).
// ============================================================================
#define TPB   256
#define JPT   8            // N / TPB / 4
#define CAP   512
#define LBUF  8

__global__ __launch_bounds__(TPB) void k_attn(const float* __restrict__ adj,
                                              const float* __restrict__ bias,
                                              float* __restrict__ out) {
    const int row  = blockIdx.x;
    const int tid  = threadIdx.x;
    const int lane = tid & 31;
    const int wid  = tid >> 5;

    __shared__ int   s_idx[CAP];
    __shared__ float s_sc[CAP];
    __shared__ int   s_woff[8];
    __shared__ int   s_total, s_fb;
    __shared__ float s_S, s_m;
    __shared__ float s_part[4 * FOUT];
    __shared__ float s_red[8];

    const float4* __restrict__ adjr = (const float4*)(adj + (size_t)row * N);
    const float f1i = g_f1[row];

    // ---- pass 1: batched loads (MLP=8), then neighbor index scan ----
    float4 av[JPT];
#pragma unroll
    for (int it = 0; it < JPT; it++)
        av[it] = adjr[it * TPB + tid];

    int lj[LBUF];
    int lcnt = 0;
#pragma unroll
    for (int it = 0; it < JPT; it++) {
        const int j0 = (it * TPB + tid) * 4;
        if (av[it].x > NEGTH) { if (lcnt < LBUF) lj[lcnt] = j0;     lcnt++; }
        if (av[it].y > NEGTH) { if (lcnt < LBUF) lj[lcnt] = j0 + 1; lcnt++; }
        if (av[it].z > NEGTH) { if (lcnt < LBUF) lj[lcnt] = j0 + 2; lcnt++; }
        if (av[it].w > NEGTH) { if (lcnt < LBUF) lj[lcnt] = j0 + 3; lcnt++; }
    }

    // ---- deterministic compaction: warp shfl-scan + 8-entry serial scan ----
    int incl = lcnt;
#pragma unroll
    for (int o = 1; o < 32; o <<= 1) {
        int v = __shfl_up_sync(0xffffffffu, incl, o);
        if (lane >= o) incl += v;
    }
    if (lane == 31) s_woff[wid] = incl;
    if (tid == 0)   s_fb = 0;
    __syncthreads();
    if (tid == 0) {
        int run = 0;
#pragma unroll
        for (int w = 0; w < 8; w++) { int t = s_woff[w]; s_woff[w] = run; run += t; }
        s_total = run;
    }
    if (lcnt > LBUF) s_fb = 1;
    __syncthreads();

    const int  total = s_total;
    const bool fb    = s_fb || (total == 0) || (total > CAP);

    if (!fb) {
        const int off = s_woff[wid] + incl - lcnt;
        for (int e = 0; e < lcnt; e++) s_idx[off + e] = lj[e];
    }
    __syncthreads();

    if (!fb) {
        // ---- scores, max, exp, sum: warp 0 only (total ~ 32) ----
        if (wid == 0) {
            float lm = -INFINITY;
            for (int e = lane; e < total; e += 32) {
                float s = f1i + g_f2[s_idx[e]];
                s = s > 0.f ? s : ALPHA * s;
                s_sc[e] = s;
                lm = fmaxf(lm, s);
            }
#pragma unroll
            for (int o = 16; o > 0; o >>= 1)
                lm = fmaxf(lm, __shfl_xor_sync(0xffffffffu, lm, o));
            float ls = 0.f;
            for (int e = lane; e < total; e += 32) {
                const float w = expf(s_sc[e] - lm);
                s_sc[e] = w;
                ls += w;
            }
#pragma unroll
            for (int o = 16; o > 0; o >>= 1)
                ls += __shfl_xor_sync(0xffffffffu, ls, o);
            if (lane == 0) s_S = ls;
        }
        __syncthreads();

        // ---- gather: 4 groups x 64 features ----
        const int g = tid >> 6, f = tid & 63;
        float acc = 0.f;
        for (int e = g; e < total; e += 4)
            acc = fmaf(s_sc[e], g_fts[(size_t)s_idx[e] * FOUT + f], acc);
        s_part[g * FOUT + f] = acc;
        __syncthreads();

        if (tid < FOUT) {
            float v = (s_part[tid] + s_part[FOUT + tid] +
                       s_part[2 * FOUT + tid] + s_part[3 * FOUT + tid]) / s_S
                      + __ldg(&bias[tid]);
            out[(size_t)row * FOUT + tid] = v > 0.f ? v : expm1f(v);
        }
    } else {
        // ---- exact streaming fallback (P ~ e^-32 per row) ----
        const float* __restrict__ adjs = adj + (size_t)row * N;
        float lm = -INFINITY;
        for (int j = tid; j < N; j += TPB) {
            float s = f1i + g_f2[j];
            s = s > 0.f ? s : ALPHA * s;
            lm = fmaxf(lm, s + adjs[j]);
        }
#pragma unroll
        for (int o = 16; o > 0; o >>= 1)
            lm = fmaxf(lm, __shfl_xor_sync(0xffffffffu, lm, o));
        if (lane == 0) s_red[wid] = lm;
        __syncthreads();
        if (tid == 0) {
            float m = s_red[0];
#pragma unroll
            for (int w = 1; w < 8; w++) m = fmaxf(m, s_red[w]);
            s_m = m;
        }
        __syncthreads();
        const float m = s_m;

        float ls = 0.f;
        for (int j = tid; j < N; j += TPB) {
            float s = f1i + g_f2[j];
            s = s > 0.f ? s : ALPHA * s;
            ls += expf(s + adjs[j] - m);
        }
#pragma unroll
        for (int o = 16; o > 0; o >>= 1)
            ls += __shfl_xor_sync(0xffffffffu, ls, o);
        if (lane == 0) s_red[wid] = ls;
        __syncthreads();
        if (tid == 0) {
            float S = 0.f;
#pragma unroll
            for (int w = 0; w < 8; w++) S += s_red[w];
            s_S = S;
        }
        __syncthreads();

        if (tid < FOUT) {
            const float invS = 1.0f / s_S;
            float acc = 0.f;
            for (int j = 0; j < N; j++) {
                float s = f1i + g_f2[j];
                s = s > 0.f ? s : ALPHA * s;
                const float w = expf(s + adjs[j] - m);
                if (w > 0.f)
                    acc = fmaf(w, g_fts[(size_t)j * FOUT + tid], acc);
            }
            float v = acc * invS + __ldg(&bias[tid]);
            out[(size_t)row * FOUT + tid] = v > 0.f ? v : expm1f(v);
        }
    }
}

// ---------------- launcher ---------------------------------------------------
extern "C" void kernel_launch(void* const* d_in, const int* in_sizes, int n_in,
                              void* d_out, int out_size) {
    const float* x    = (const float*)d_in[0];  // [1, N, FIN]
    const float* adj  = (const float*)d_in[1];  // [1, N, N]
    const float* W    = (const float*)d_in[2];  // [FIN, FOUT]
    const float* a1   = (const float*)d_in[3];  // [FOUT, 1]
    const float* b1   = (const float*)d_in[4];  // [1]
    const float* a2   = (const float*)d_in[5];  // [FOUT, 1]
    const float* b2   = (const float*)d_in[6];  // [1]
    const float* bias = (const float*)d_in[7];  // [FOUT]
    float* out = (float*)d_out;                 // [1, N, FOUT]

    k_proj<<<N / TR, 128>>>(x, W, a1, b1, a2, b2);
    k_attn<<<N, TPB>>>(adj, bias, out);
}

// round 4
// speedup vs baseline: 1.5748x; 1.0004x over previous
#include <cuda_runtime.h>
#include <math.h>

#define N      8192
#define FIN    256
#define FOUT   64
#define NEGTH  (-1e8f)      // adj: 0.0f for neighbor, -1e9 otherwise
#define ALPHA  0.2f

// ---------------- scratch (static __device__, allocation-free) --------------
__device__ __align__(16) static float g_fts[N * FOUT];
__device__ __align__(16) static float g_f1[N];
__device__ __align__(16) static float g_f2[N];

// ============================================================================
// kernel 1: fts = x @ W  (+ fused f1/f2).  32 rows x 64 f per 128-thread
// block, 4x4 micro-tile, double-buffered smem with register-staged prefetch
// (ONE __syncthreads per K-chunk).
// ============================================================================
#define TR  32
#define KC  32
#define NCH (FIN / KC)        // 8 K-chunks
__global__ __launch_bounds__(128) void k_proj(
        const float* __restrict__ x,  const float* __restrict__ W,
        const float* __restrict__ a1, const float* __restrict__ b1,
        const float* __restrict__ a2, const float* __restrict__ b2) {
    __shared__ float xs[2][TR][KC + 1];   // [buf][row][k]
    __shared__ float ws[2][KC * FOUT];    // [buf][k*64+f]

    const int tid  = threadIdx.x;
    const int row0 = blockIdx.x * TR;
    const int fg   = tid & 15;            // 16 f-groups
    const int rg   = tid >> 4;            // 8 row-groups
    const int f0   = fg * 4;
    const int r0   = rg * 4;

    // load-assignment for staging
    const int xk  = tid & 31;             // k within chunk (coalesced)
    const int xr0 = tid >> 5;             // base row (0..3), rows xr0+4i
    const float4* __restrict__ W4 = (const float4*)W;

    float  xbuf[8];
    float4 wbuf[4];

    // prefetch chunk 0
#pragma unroll
    for (int i = 0; i < 8; i++)
        xbuf[i] = x[(size_t)(row0 + xr0 + 4 * i) * FIN + xk];
#pragma unroll
    for (int i = 0; i < 4; i++)
        wbuf[i] = W4[tid + i * 128];

    float acc[4][4] = {};

#pragma unroll
    for (int c = 0; c < NCH; c++) {
        const int b = c & 1;
        // commit staged regs -> smem buf b
#pragma unroll
        for (int i = 0; i < 8; i++)
            xs[b][xr0 + 4 * i][xk] = xbuf[i];
        {
            float4* ws4 = (float4*)ws[b];
#pragma unroll
            for (int i = 0; i < 4; i++)
                ws4[tid + i * 128] = wbuf[i];
        }
        __syncthreads();

        // prefetch chunk c+1 (overlaps with compute below)
        if (c < NCH - 1) {
            const int kc = (c + 1) * KC;
#pragma unroll
            for (int i = 0; i < 8; i++)
                xbuf[i] = x[(size_t)(row0 + xr0 + 4 * i) * FIN + kc + xk];
#pragma unroll
            for (int i = 0; i < 4; i++)
                wbuf[i] = W4[kc * 16 + tid + i * 128];
        }

        // compute
#pragma unroll
        for (int k = 0; k < KC; k++) {
            const float4 wv = *(const float4*)&ws[b][k * FOUT + f0];
            float xr[4];
#pragma unroll
            for (int r = 0; r < 4; r++) xr[r] = xs[b][r0 + r][k];
            const float wf[4] = {wv.x, wv.y, wv.z, wv.w};
#pragma unroll
            for (int r = 0; r < 4; r++)
#pragma unroll
                for (int j = 0; j < 4; j++)
                    acc[r][j] = fmaf(xr[r], wf[j], acc[r][j]);
        }
        // single sync per iter: next store targets buf b^1, whose last readers
        // finished before the sync we already passed.
        __syncthreads();
    }

    // store fts
#pragma unroll
    for (int r = 0; r < 4; r++) {
        float4 v = make_float4(acc[r][0], acc[r][1], acc[r][2], acc[r][3]);
        *(float4*)&g_fts[(size_t)(row0 + r0 + r) * FOUT + f0] = v;
    }

    // fused f1/f2: partial over this thread's 4 f's, reduce across 16 fg lanes
    const float4 a1v = *(const float4*)&a1[f0];
    const float4 a2v = *(const float4*)&a2[f0];
    float p1[4], p2[4];
#pragma unroll
    for (int r = 0; r < 4; r++) {
        p1[r] = acc[r][0]*a1v.x + acc[r][1]*a1v.y + acc[r][2]*a1v.z + acc[r][3]*a1v.w;
        p2[r] = acc[r][0]*a2v.x + acc[r][1]*a2v.y + acc[r][2]*a2v.z + acc[r][3]*a2v.w;
    }
#pragma unroll
    for (int o = 1; o < 16; o <<= 1) {
#pragma unroll
        for (int r = 0; r < 4; r++) {
            p1[r] += __shfl_xor_sync(0xffffffffu, p1[r], o);
            p2[r] += __shfl_xor_sync(0xffffffffu, p2[r], o);
        }
    }
    if (fg == 0) {
        const float bb1 = __ldg(b1), bb2 = __ldg(b2);
#pragma unroll
        for (int r = 0; r < 4; r++) {
            g_f1[row0 + r0 + r] = p1[r] + bb1;
            g_f2[row0 + r0 + r] = p2[r] + bb2;
        }
    }
}

// ============================================================================
// kernel 2: fused sparse softmax + SpMM + elu. One block (512 thr) per row.
// Neighbor detection via 16-bit mask (popc/ffs) — no serial predicate chain.
// ============================================================================
#define TPB   512
#define JPT   4              // N / TPB / 4
#define CAP   512

__global__ __launch_bounds__(TPB) void k_attn(const float* __restrict__ adj,
                                              const float* __restrict__ bias,
                                              float* __restrict__ out) {
    const int row  = blockIdx.x;
    const int tid  = threadIdx.x;
    const int lane = tid & 31;
    const int wid  = tid >> 5;           // 0..15

    __shared__ int   s_idx[CAP];
    __shared__ float s_sc[CAP];
    __shared__ int   s_woff[16];
    __shared__ int   s_total;
    __shared__ float s_S, s_m;
    __shared__ float s_part[8 * FOUT];
    __shared__ float s_red[16];

    const float4* __restrict__ adjr = (const float4*)(adj + (size_t)row * N);
    const float f1i = g_f1[row];

    // ---- batched streaming loads (MLP=4/thread, 2048 threads worth) ----
    float4 av[JPT];
#pragma unroll
    for (int it = 0; it < JPT; it++)
        av[it] = adjr[it * TPB + tid];

    // ---- independent-compare mask build ----
    unsigned mask = 0;
#pragma unroll
    for (int it = 0; it < JPT; it++) {
        unsigned nb = (av[it].x > NEGTH ? 1u : 0u)
                    | (av[it].y > NEGTH ? 2u : 0u)
                    | (av[it].z > NEGTH ? 4u : 0u)
                    | (av[it].w > NEGTH ? 8u : 0u);
        mask |= nb << (it * 4);
    }
    const int lcnt = __popc(mask);

    // ---- deterministic compaction: warp shfl-scan + 16-entry serial scan ----
    int incl = lcnt;
#pragma unroll
    for (int o = 1; o < 32; o <<= 1) {
        int v = __shfl_up_sync(0xffffffffu, incl, o);
        if (lane >= o) incl += v;
    }
    if (lane == 31) s_woff[wid] = incl;
    __syncthreads();
    if (tid == 0) {
        int run = 0;
#pragma unroll
        for (int w = 0; w < 16; w++) { int t = s_woff[w]; s_woff[w] = run; run += t; }
        s_total = run;
    }
    __syncthreads();

    const int  total = s_total;
    const bool ok    = (total > 0) && (total <= CAP);

    if (ok && lcnt) {
        int off = s_woff[wid] + incl - lcnt;
        unsigned mm = mask;
        for (int e = 0; e < lcnt; e++) {
            const int b = __ffs(mm) - 1;
            mm &= mm - 1;
            s_idx[off + e] = (b >> 2) * (TPB * 4) + tid * 4 + (b & 3);
        }
    }
    __syncthreads();

    if (ok) {
        // ---- scores, max, exp, sum on warp 0 (total ~ 32) ----
        if (wid == 0) {
            float lm = -INFINITY;
            for (int e = lane; e < total; e += 32) {
                float s = f1i + g_f2[s_idx[e]];
                s = s > 0.f ? s : ALPHA * s;
                s_sc[e] = s;
                lm = fmaxf(lm, s);
            }
#pragma unroll
            for (int o = 16; o > 0; o >>= 1)
                lm = fmaxf(lm, __shfl_xor_sync(0xffffffffu, lm, o));
            float ls = 0.f;
            for (int e = lane; e < total; e += 32) {
                const float w = expf(s_sc[e] - lm);
                s_sc[e] = w;
                ls += w;
            }
#pragma unroll
            for (int o = 16; o > 0; o >>= 1)
                ls += __shfl_xor_sync(0xffffffffu, ls, o);
            if (lane == 0) s_S = ls;
        }
        __syncthreads();

        // ---- gather: 8 groups x 64 features ----
        const int g = tid >> 6, f = tid & 63;
        float acc = 0.f;
        for (int e = g; e < total; e += 8)
            acc = fmaf(s_sc[e], g_fts[(size_t)s_idx[e] * FOUT + f], acc);
        s_part[g * FOUT + f] = acc;
        __syncthreads();

        if (tid < FOUT) {
            float v = 0.f;
#pragma unroll
            for (int g2 = 0; g2 < 8; g2++) v += s_part[g2 * FOUT + tid];
            v = v / s_S + __ldg(&bias[tid]);
            out[(size_t)row * FOUT + tid] = v > 0.f ? v : expm1f(v);
        }
    } else {
        // ---- exact streaming fallback (P ~ 1e-14 per row) ----
        const float* __restrict__ adjs = adj + (size_t)row * N;
        float lm = -INFINITY;
        for (int j = tid; j < N; j += TPB) {
            float s = f1i + g_f2[j];
            s = s > 0.f ? s : ALPHA * s;
            lm = fmaxf(lm, s + adjs[j]);
        }
#pragma unroll
        for (int o = 16; o > 0; o >>= 1)
            lm = fmaxf(lm, __shfl_xor_sync(0xffffffffu, lm, o));
        if (lane == 0) s_red[wid] = lm;
        __syncthreads();
        if (tid == 0) {
            float m = s_red[0];
#pragma unroll
            for (int w = 1; w < 16; w++) m = fmaxf(m, s_red[w]);
            s_m = m;
        }
        __syncthreads();
        const float m = s_m;

        float ls = 0.f;
        for (int j = tid; j < N; j += TPB) {
            float s = f1i + g_f2[j];
            s = s > 0.f ? s : ALPHA * s;
            ls += expf(s + adjs[j] - m);
        }
#pragma unroll
        for (int o = 16; o > 0; o >>= 1)
            ls += __shfl_xor_sync(0xffffffffu, ls, o);
        if (lane == 0) s_red[wid] = ls;
        __syncthreads();
        if (tid == 0) {
            float S = 0.f;
#pragma unroll
            for (int w = 0; w < 16; w++) S += s_red[w];
            s_S = S;
        }
        __syncthreads();

        if (tid < FOUT) {
            const float invS = 1.0f / s_S;
            float acc = 0.f;
            for (int j = 0; j < N; j++) {
                float s = f1i + g_f2[j];
                s = s > 0.f ? s : ALPHA * s;
                const float w = expf(s + adjs[j] - m);
                if (w > 0.f)
                    acc = fmaf(w, g_fts[(size_t)j * FOUT + tid], acc);
            }
            float v = acc * invS + __ldg(&bias[tid]);
            out[(size_t)row * FOUT + tid] = v > 0.f ? v : expm1f(v);
        }
    }
}

// ---------------- launcher ---------------------------------------------------
extern "C" void kernel_launch(void* const* d_in, const int* in_sizes, int n_in,
                              void* d_out, int out_size) {
    const float* x    = (const float*)d_in[0];  // [1, N, FIN]
    const float* adj  = (const float*)d_in[1];  // [1, N, N]
    const float* W    = (const float*)d_in[2];  // [FIN, FOUT]
    const float* a1   = (const float*)d_in[3];  // [FOUT, 1]
    const float* b1   = (const float*)d_in[4];  // [1]
    const float* a2   = (const float*)d_in[5];  // [FOUT, 1]
    const float* b2   = (const float*)d_in[6];  // [1]
    const float* bias = (const float*)d_in[7];  // [FOUT]
    float* out = (float*)d_out;                 // [1, N, FOUT]

    k_proj<<<N / TR, 128>>>(x, W, a1, b1, a2, b2);
    k_attn<<<N, TPB>>>(adj, bias, out);
}

// round 5
// speedup vs baseline: 1.6752x; 1.0638x over previous
#include <cuda_runtime.h>
#include <math.h>

#define N      8192
#define FIN    256
#define FOUT   64
#define NEGTH  (-1e8f)      // adj: 0.0f neighbor, -1e9 otherwise
#define ALPHA  0.2f

#define NPROJ  128          // proj blocks in fused kernel
#define TR     64           // rows per proj block
#define KC     32
#define NCH    (FIN / KC)
#define NSCAN  (N / 8)      // 1024 scan blocks (8 warps x 1 row)
#define CAP    96           // neighbor capacity per row (E[n]=32)

// ---------------- scratch (static __device__, allocation-free) --------------
__device__ __align__(16) static float g_fts[N * FOUT];
__device__ __align__(16) static float g_f1[N];
__device__ __align__(16) static float g_f2[N];
__device__ __align__(16) static float g_w1[FIN];
__device__ __align__(16) static float g_w2[FIN];
__device__ static int g_done;

// ============================================================================
// k_pre:  w1 = W @ a1,  w2 = W @ a2     (associativity: f1 = x @ w1 + b1)
// ============================================================================
__global__ void k_pre(const float* __restrict__ W,
                      const float* __restrict__ a1, const float* __restrict__ a2) {
    const int k = blockIdx.x * 32 + threadIdx.x;      // 8 blocks x 32
    const float4* __restrict__ Wr = (const float4*)(W + (size_t)k * FOUT);
    const float4* __restrict__ A1 = (const float4*)a1;
    const float4* __restrict__ A2 = (const float4*)a2;
    float s1 = 0.f, s2 = 0.f;
#pragma unroll
    for (int i = 0; i < 16; i++) {
        const float4 w = Wr[i], u = A1[i], v = A2[i];
        s1 += w.x*u.x + w.y*u.y + w.z*u.z + w.w*u.w;
        s2 += w.x*v.x + w.y*v.y + w.z*v.z + w.w*v.w;
    }
    g_w1[k] = s1;
    g_w2[k] = s2;
}

// ============================================================================
// k_f12:  f1[i] = x[i,:]@w1 + b1,  f2[i] = x[i,:]@w2 + b2.  Warp per row.
// Also resets the proj-done flag for this launch (graph-replay safe).
// ============================================================================
__global__ __launch_bounds__(256) void k_f12(const float* __restrict__ x,
                                             const float* __restrict__ b1,
                                             const float* __restrict__ b2) {
    if (blockIdx.x == 0 && threadIdx.x == 0) g_done = 0;
    const int wid  = threadIdx.x >> 5;
    const int lane = threadIdx.x & 31;
    const int row  = blockIdx.x * 8 + wid;

    const float4* __restrict__ xr = (const float4*)(x + (size_t)row * FIN);
    const float4* __restrict__ w1 = (const float4*)g_w1;
    const float4* __restrict__ w2 = (const float4*)g_w2;

    float s1 = 0.f, s2 = 0.f;
#pragma unroll
    for (int i = 0; i < 2; i++) {
        const float4 xv = xr[lane * 2 + i];
        const float4 u  = w1[lane * 2 + i];
        const float4 v  = w2[lane * 2 + i];
        s1 += xv.x*u.x + xv.y*u.y + xv.z*u.z + xv.w*u.w;
        s2 += xv.x*v.x + xv.y*v.y + xv.z*v.z + xv.w*v.w;
    }
#pragma unroll
    for (int o = 16; o > 0; o >>= 1) {
        s1 += __shfl_xor_sync(0xffffffffu, s1, o);
        s2 += __shfl_xor_sync(0xffffffffu, s2, o);
    }
    if (lane == 0) {
        g_f1[row] = s1 + __ldg(b1);
        g_f2[row] = s2 + __ldg(b2);
    }
}

// ============================================================================
// k_main (fused, block-specialized):
//   bid <  NPROJ : fts = x @ W   (64 rows, 4x4 micro-tile, double-buffered)
//   bid >= NPROJ : warp-per-row adjacency scan + softmax (fts-independent),
//                  then wait g_done, then gather + elu.
// ============================================================================
__global__ __launch_bounds__(256) void k_main(
        const float* __restrict__ x,   const float* __restrict__ W,
        const float* __restrict__ adj, const float* __restrict__ bias,
        float* __restrict__ out) {
    __shared__ float xs[2][TR][KC + 1];
    __shared__ float ws[2][KC * FOUT];
    __shared__ int   s_idx[8][CAP];
    __shared__ float s_wt[8][CAP];

    const int tid  = threadIdx.x;
    const int lane = tid & 31;
    const int wid  = tid >> 5;

    if (blockIdx.x < NPROJ) {
        // ------------------------- projection role -------------------------
        const int row0 = blockIdx.x * TR;
        const int fg = tid & 15, rg = tid >> 4;
        const int f0 = fg * 4,   r0 = rg * 4;
        const int xk = tid & 31, xr0 = tid >> 5;          // staging map
        const float4* __restrict__ W4 = (const float4*)W;

        float  xbuf[8];
        float4 wbuf[2];
#pragma unroll
        for (int i = 0; i < 8; i++)
            xbuf[i] = x[(size_t)(row0 + xr0 + 8 * i) * FIN + xk];
#pragma unroll
        for (int i = 0; i < 2; i++)
            wbuf[i] = W4[tid + i * 256];

        float acc[4][4] = {};
#pragma unroll
        for (int c = 0; c < NCH; c++) {
            const int b = c & 1;
#pragma unroll
            for (int i = 0; i < 8; i++)
                xs[b][xr0 + 8 * i][xk] = xbuf[i];
            {
                float4* ws4 = (float4*)ws[b];
#pragma unroll
                for (int i = 0; i < 2; i++)
                    ws4[tid + i * 256] = wbuf[i];
            }
            __syncthreads();

            if (c < NCH - 1) {
                const int kc = (c + 1) * KC;
#pragma unroll
                for (int i = 0; i < 8; i++)
                    xbuf[i] = x[(size_t)(row0 + xr0 + 8 * i) * FIN + kc + xk];
#pragma unroll
                for (int i = 0; i < 2; i++)
                    wbuf[i] = W4[kc * 16 + tid + i * 256];
            }

#pragma unroll
            for (int k = 0; k < KC; k++) {
                const float4 wv = *(const float4*)&ws[b][k * FOUT + f0];
                float xr[4];
#pragma unroll
                for (int r = 0; r < 4; r++) xr[r] = xs[b][r0 + r][k];
                const float wf[4] = {wv.x, wv.y, wv.z, wv.w};
#pragma unroll
                for (int r = 0; r < 4; r++)
#pragma unroll
                    for (int j = 0; j < 4; j++)
                        acc[r][j] = fmaf(xr[r], wf[j], acc[r][j]);
            }
            __syncthreads();
        }

#pragma unroll
        for (int r = 0; r < 4; r++) {
            float4 v = make_float4(acc[r][0], acc[r][1], acc[r][2], acc[r][3]);
            *(float4*)&g_fts[(size_t)(row0 + r0 + r) * FOUT + f0] = v;
        }
        __threadfence();
        __syncthreads();
        if (tid == 0) atomicAdd(&g_done, 1);
        return;
    }

    // --------------------------- scan/finish role ---------------------------
    const int row = (blockIdx.x - NPROJ) * 8 + wid;
    const float f1i = g_f1[row];
    const float4* __restrict__ adjr = (const float4*)(adj + (size_t)row * N);

    // stream 32KB row, build 256-bit neighbor mask (independent compares)
    unsigned m[8];
#pragma unroll
    for (int b = 0; b < 8; b++) {
        float4 av[8];
#pragma unroll
        for (int u = 0; u < 8; u++)
            av[u] = __ldcs(&adjr[(b * 8 + u) * 32 + lane]);
        unsigned w = 0;
#pragma unroll
        for (int u = 0; u < 8; u++) {
            unsigned nb = (av[u].x > NEGTH ? 1u : 0u)
                        | (av[u].y > NEGTH ? 2u : 0u)
                        | (av[u].z > NEGTH ? 4u : 0u)
                        | (av[u].w > NEGTH ? 8u : 0u);
            w |= nb << (u * 4);
        }
        m[b] = w;
    }
    int lcnt = 0;
#pragma unroll
    for (int b = 0; b < 8; b++) lcnt += __popc(m[b]);

    // warp exclusive scan
    int incl = lcnt;
#pragma unroll
    for (int o = 1; o < 32; o <<= 1) {
        int v = __shfl_up_sync(0xffffffffu, incl, o);
        if (lane >= o) incl += v;
    }
    const int total = __shfl_sync(0xffffffffu, incl, 31);
    const int off   = incl - lcnt;
    const bool ok   = (total > 0) && (total <= CAP);

    float S = 0.f;
    if (ok) {
        if (lcnt) {
            int o = off;
#pragma unroll
            for (int b = 0; b < 8; b++) {
                unsigned mw = m[b];
                while (mw) {
                    const int p = __ffs(mw) - 1;
                    mw &= mw - 1;
                    s_idx[wid][o++] = (b * 8 + (p >> 2)) * 128 + lane * 4 + (p & 3);
                }
            }
        }
        __syncwarp();

        // warp softmax over <=96 entries
        float lm = -INFINITY;
        for (int e = lane; e < total; e += 32) {
            float s = f1i + g_f2[s_idx[wid][e]];
            s = s > 0.f ? s : ALPHA * s;
            s_wt[wid][e] = s;
            lm = fmaxf(lm, s);
        }
#pragma unroll
        for (int o = 16; o > 0; o >>= 1)
            lm = fmaxf(lm, __shfl_xor_sync(0xffffffffu, lm, o));
        float ls = 0.f;
        for (int e = lane; e < total; e += 32) {
            const float w = expf(s_wt[wid][e] - lm);
            s_wt[wid][e] = w;
            ls += w;
        }
#pragma unroll
        for (int o = 16; o > 0; o >>= 1)
            ls += __shfl_xor_sync(0xffffffffu, ls, o);
        S = ls;
        __syncwarp();
    }

    // wait for fts (proj blocks never wait; bids 0..127 are wave-1 residents)
    if (lane == 0)
        while (*(volatile int*)&g_done != NPROJ) __nanosleep(256);
    __syncwarp();
    __threadfence();

    if (ok) {
        const float invS = 1.0f / S;
        float acc0 = 0.f, acc1 = 0.f;
        for (int e = 0; e < total; e++) {
            const float w = s_wt[wid][e];
            const float* fr = &g_fts[(size_t)s_idx[wid][e] * FOUT];
            acc0 = fmaf(w, fr[lane],      acc0);
            acc1 = fmaf(w, fr[lane + 32], acc1);
        }
        float v0 = acc0 * invS + __ldg(&bias[lane]);
        float v1 = acc1 * invS + __ldg(&bias[lane + 32]);
        out[(size_t)row * FOUT + lane]      = v0 > 0.f ? v0 : expm1f(v0);
        out[(size_t)row * FOUT + lane + 32] = v1 > 0.f ? v1 : expm1f(v1);
    } else {
        // exact warp-scoped streaming fallback (P ~ 1e-10)
        const float* __restrict__ adjs = adj + (size_t)row * N;
        float lm = -INFINITY;
        for (int j = lane; j < N; j += 32) {
            float s = f1i + g_f2[j];
            s = s > 0.f ? s : ALPHA * s;
            lm = fmaxf(lm, s + adjs[j]);
        }
#pragma unroll
        for (int o = 16; o > 0; o >>= 1)
            lm = fmaxf(lm, __shfl_xor_sync(0xffffffffu, lm, o));
        float ls = 0.f;
        for (int j = lane; j < N; j += 32) {
            float s = f1i + g_f2[j];
            s = s > 0.f ? s : ALPHA * s;
            ls += expf(s + adjs[j] - lm);
        }
#pragma unroll
        for (int o = 16; o > 0; o >>= 1)
            ls += __shfl_xor_sync(0xffffffffu, ls, o);
        const float invS = 1.0f / ls;
        float acc0 = 0.f, acc1 = 0.f;
        for (int j = 0; j < N; j++) {
            float s = f1i + g_f2[j];
            s = s > 0.f ? s : ALPHA * s;
            const float w = expf(s + adjs[j] - lm);
            if (w > 0.f) {
                const float* fr = &g_fts[(size_t)j * FOUT];
                acc0 = fmaf(w, fr[lane],      acc0);
                acc1 = fmaf(w, fr[lane + 32], acc1);
            }
        }
        float v0 = acc0 * invS + __ldg(&bias[lane]);
        float v1 = acc1 * invS + __ldg(&bias[lane + 32]);
        out[(size_t)row * FOUT + lane]      = v0 > 0.f ? v0 : expm1f(v0);
        out[(size_t)row * FOUT + lane + 32] = v1 > 0.f ? v1 : expm1f(v1);
    }
}

// ---------------- launcher ---------------------------------------------------
extern "C" void kernel_launch(void* const* d_in, const int* in_sizes, int n_in,
                              void* d_out, int out_size) {
    const float* x    = (const float*)d_in[0];
    const float* adj  = (const float*)d_in[1];
    const float* W    = (const float*)d_in[2];
    const float* a1   = (const float*)d_in[3];
    const float* b1   = (const float*)d_in[4];
    const float* a2   = (const float*)d_in[5];
    const float* b2   = (const float*)d_in[6];
    const float* bias = (const float*)d_in[7];
    float* out = (float*)d_out;

    k_pre <<<FIN / 32, 32>>>(W, a1, a2);
    k_f12 <<<N / 8, 256>>>(x, b1, b2);
    k_main<<<NPROJ + NSCAN, 256>>>(x, W, adj, bias, out);
}

// round 6
// speedup vs baseline: 1.9426x; 1.1596x over previous
#include <cuda_runtime.h>
#include <math.h>

#define N      8192
#define FIN    256
#define FOUT   64
#define NEGTH  (-1e8f)      // adj: 0.0f neighbor, -1e9 otherwise
#define ALPHA  0.2f

#define NPROJ  128          // projection blocks (bid < NPROJ)
#define NSCANB 512          // scan blocks; 8 warps x 2 rows each = 8192 rows
#define NBLK   (NPROJ + NSCANB)
#define TR     64           // rows per proj block
#define KC     32
#define NCH    (FIN / KC)
#define CAP    96           // neighbor capacity/row (E=32, 11 sigma headroom)

// ---------------- scratch (static __device__, allocation-free) --------------
__device__ __align__(16) static float g_fts[N * FOUT];
__device__ __align__(16) static float g_f1[N];
__device__ __align__(16) static float g_f2[N];
__device__ static int g_done;   // proj blocks finished (reset by last scan blk)
__device__ static int g_fin;    // scan blocks finished

// shared-memory overlay: proj tile vs scan lists never coexist in a block
struct ProjS {
    float xs[TR][KC + 1];       // 8448 B
    float ws[KC * FOUT];        // 8192 B
};
struct ScanS {
    int   idx[16][CAP];         // 16 row-slots (8 warps x 2 rows)
    float wt[16][CAP];
};

__global__ __launch_bounds__(256) void k_main(
        const float* __restrict__ x,   const float* __restrict__ W,
        const float* __restrict__ adj,
        const float* __restrict__ a1,  const float* __restrict__ b1,
        const float* __restrict__ a2,  const float* __restrict__ b2,
        const float* __restrict__ bias, float* __restrict__ out) {
    __shared__ __align__(16) char smem_raw[sizeof(ProjS) > sizeof(ScanS)
                                           ? sizeof(ProjS) : sizeof(ScanS)];
    const int tid  = threadIdx.x;
    const int lane = tid & 31;
    const int wid  = tid >> 5;

    if (blockIdx.x < NPROJ) {
        // ========================= projection role ==========================
        ProjS& S = *reinterpret_cast<ProjS*>(smem_raw);
        const int row0 = blockIdx.x * TR;
        const int fg = tid & 15, rg = tid >> 4;
        const int f0 = fg * 4,   r0 = rg * 4;
        const int xk = tid & 31, xr0 = tid >> 5;       // x-tile loader map
        const float4* __restrict__ W4 = (const float4*)W;

        float acc[4][4] = {};
#pragma unroll
        for (int c = 0; c < NCH; c++) {
            const int kc = c * KC;
            __syncthreads();
#pragma unroll
            for (int i = 0; i < 8; i++)
                S.xs[xr0 + 8 * i][xk] = x[(size_t)(row0 + xr0 + 8 * i) * FIN + kc + xk];
            {
                float4* ws4 = (float4*)S.ws;
#pragma unroll
                for (int i = 0; i < 2; i++)
                    ws4[tid + i * 256] = W4[kc * 16 + tid + i * 256];
            }
            __syncthreads();
#pragma unroll
            for (int k = 0; k < KC; k++) {
                const float4 wv = *(const float4*)&S.ws[k * FOUT + f0];
                float xr[4];
#pragma unroll
                for (int r = 0; r < 4; r++) xr[r] = S.xs[r0 + r][k];
                const float wf[4] = {wv.x, wv.y, wv.z, wv.w};
#pragma unroll
                for (int r = 0; r < 4; r++)
#pragma unroll
                    for (int j = 0; j < 4; j++)
                        acc[r][j] = fmaf(xr[r], wf[j], acc[r][j]);
            }
        }

        // store fts
#pragma unroll
        for (int r = 0; r < 4; r++) {
            float4 v = make_float4(acc[r][0], acc[r][1], acc[r][2], acc[r][3]);
            *(float4*)&g_fts[(size_t)(row0 + r0 + r) * FOUT + f0] = v;
        }

        // fused f1/f2 from register accumulators (exact reference path)
        const float4 a1v = *(const float4*)&a1[f0];
        const float4 a2v = *(const float4*)&a2[f0];
        float p1[4], p2[4];
#pragma unroll
        for (int r = 0; r < 4; r++) {
            p1[r] = acc[r][0]*a1v.x + acc[r][1]*a1v.y + acc[r][2]*a1v.z + acc[r][3]*a1v.w;
            p2[r] = acc[r][0]*a2v.x + acc[r][1]*a2v.y + acc[r][2]*a2v.z + acc[r][3]*a2v.w;
        }
#pragma unroll
        for (int o = 1; o < 16; o <<= 1) {
#pragma unroll
            for (int r = 0; r < 4; r++) {
                p1[r] += __shfl_xor_sync(0xffffffffu, p1[r], o);
                p2[r] += __shfl_xor_sync(0xffffffffu, p2[r], o);
            }
        }
        if (fg == 0) {
            const float bb1 = __ldg(b1), bb2 = __ldg(b2);
#pragma unroll
            for (int r = 0; r < 4; r++) {
                g_f1[row0 + r0 + r] = p1[r] + bb1;
                g_f2[row0 + r0 + r] = p2[r] + bb2;
            }
        }
        __threadfence();
        __syncthreads();
        if (tid == 0) atomicAdd(&g_done, 1);
        return;
    }

    // =========================== scan/finish role ===========================
    ScanS& S = *reinterpret_cast<ScanS*>(smem_raw);
    const int base = ((blockIdx.x - NPROJ) * 8 + wid) * 2;   // 2 rows per warp
    int cnt[2];

    // ---- phase A: stream both adj rows, build masks, compact (fts-free) ----
#pragma unroll
    for (int r = 0; r < 2; r++) {
        const int row  = base + r;
        const int slot = wid * 2 + r;
        const float4* __restrict__ adjr = (const float4*)(adj + (size_t)row * N);

        unsigned m[8];
#pragma unroll
        for (int b = 0; b < 8; b++) {
            float4 av[8];
#pragma unroll
            for (int u = 0; u < 8; u++)
                av[u] = __ldcs(&adjr[(b * 8 + u) * 32 + lane]);
            unsigned w = 0;
#pragma unroll
            for (int u = 0; u < 8; u++) {
                unsigned nb = (av[u].x > NEGTH ? 1u : 0u)
                            | (av[u].y > NEGTH ? 2u : 0u)
                            | (av[u].z > NEGTH ? 4u : 0u)
                            | (av[u].w > NEGTH ? 8u : 0u);
                w |= nb << (u * 4);
            }
            m[b] = w;
        }
        int lcnt = 0;
#pragma unroll
        for (int b = 0; b < 8; b++) lcnt += __popc(m[b]);

        int incl = lcnt;
#pragma unroll
        for (int o = 1; o < 32; o <<= 1) {
            int v = __shfl_up_sync(0xffffffffu, incl, o);
            if (lane >= o) incl += v;
        }
        cnt[r] = __shfl_sync(0xffffffffu, incl, 31);
        if (cnt[r] > 0 && cnt[r] <= CAP && lcnt) {
            int o = incl - lcnt;
#pragma unroll
            for (int b = 0; b < 8; b++) {
                unsigned mw = m[b];
                while (mw) {
                    const int p = __ffs(mw) - 1;
                    mw &= mw - 1;
                    S.idx[slot][o++] = (b * 8 + (p >> 2)) * 128 + lane * 4 + (p & 3);
                }
            }
        }
        __syncwarp();
    }

    // ---- wait for projection (fts, f1, f2) ----
    if (lane == 0)
        while (*(volatile int*)&g_done != NPROJ) __nanosleep(128);
    __syncwarp();
    __threadfence();

    // ---- phase B: softmax + gather per row ----
#pragma unroll
    for (int r = 0; r < 2; r++) {
        const int row   = base + r;
        const int slot  = wid * 2 + r;
        const int total = cnt[r];
        const float f1i = g_f1[row];

        if (total > 0 && total <= CAP) {
            float lm = -INFINITY;
            for (int e = lane; e < total; e += 32) {
                float s = f1i + g_f2[S.idx[slot][e]];
                s = s > 0.f ? s : ALPHA * s;
                S.wt[slot][e] = s;
                lm = fmaxf(lm, s);
            }
#pragma unroll
            for (int o = 16; o > 0; o >>= 1)
                lm = fmaxf(lm, __shfl_xor_sync(0xffffffffu, lm, o));
            float ls = 0.f;
            for (int e = lane; e < total; e += 32) {
                const float w = expf(S.wt[slot][e] - lm);
                S.wt[slot][e] = w;
                ls += w;
            }
#pragma unroll
            for (int o = 16; o > 0; o >>= 1)
                ls += __shfl_xor_sync(0xffffffffu, ls, o);
            __syncwarp();

            const float invS = 1.0f / ls;
            float acc0 = 0.f, acc1 = 0.f;
            for (int e = 0; e < total; e++) {
                const float w = S.wt[slot][e];
                const float* fr = &g_fts[(size_t)S.idx[slot][e] * FOUT];
                acc0 = fmaf(w, fr[lane],      acc0);
                acc1 = fmaf(w, fr[lane + 32], acc1);
            }
            float v0 = acc0 * invS + __ldg(&bias[lane]);
            float v1 = acc1 * invS + __ldg(&bias[lane + 32]);
            out[(size_t)row * FOUT + lane]      = v0 > 0.f ? v0 : expm1f(v0);
            out[(size_t)row * FOUT + lane + 32] = v1 > 0.f ? v1 : expm1f(v1);
        } else {
            // exact warp-scoped streaming fallback (P ~ 1e-10 per row)
            const float* __restrict__ adjs = adj + (size_t)row * N;
            float lm = -INFINITY;
            for (int j = lane; j < N; j += 32) {
                float s = f1i + g_f2[j];
                s = s > 0.f ? s : ALPHA * s;
                lm = fmaxf(lm, s + adjs[j]);
            }
#pragma unroll
            for (int o = 16; o > 0; o >>= 1)
                lm = fmaxf(lm, __shfl_xor_sync(0xffffffffu, lm, o));
            float ls = 0.f;
            for (int j = lane; j < N; j += 32) {
                float s = f1i + g_f2[j];
                s = s > 0.f ? s : ALPHA * s;
                ls += expf(s + adjs[j] - lm);
            }
#pragma unroll
            for (int o = 16; o > 0; o >>= 1)
                ls += __shfl_xor_sync(0xffffffffu, ls, o);
            const float invS = 1.0f / ls;
            float acc0 = 0.f, acc1 = 0.f;
            for (int j = 0; j < N; j++) {
                float s = f1i + g_f2[j];
                s = s > 0.f ? s : ALPHA * s;
                const float w = expf(s + adjs[j] - lm);
                if (w > 0.f) {
                    const float* fr = &g_fts[(size_t)j * FOUT];
                    acc0 = fmaf(w, fr[lane],      acc0);
                    acc1 = fmaf(w, fr[lane + 32], acc1);
                }
            }
            float v0 = acc0 * invS + __ldg(&bias[lane]);
            float v1 = acc1 * invS + __ldg(&bias[lane + 32]);
            out[(size_t)row * FOUT + lane]      = v0 > 0.f ? v0 : expm1f(v0);
            out[(size_t)row * FOUT + lane + 32] = v1 > 0.f ? v1 : expm1f(v1);
        }
    }

    // ---- self-cleaning flags for graph replay (last scan block resets) ----
    __syncthreads();
    if (tid == 0) {
        const int v = atomicAdd(&g_fin, 1);
        if (v == NSCANB - 1) {      // all scan blocks already passed the wait
            g_done = 0;
            g_fin  = 0;
        }
    }
}

// ---------------- launcher ---------------------------------------------------
extern "C" void kernel_launch(void* const* d_in, const int* in_sizes, int n_in,
                              void* d_out, int out_size) {
    const float* x    = (const float*)d_in[0];
    const float* adj  = (const float*)d_in[1];
    const float* W    = (const float*)d_in[2];
    const float* a1   = (const float*)d_in[3];
    const float* b1   = (const float*)d_in[4];
    const float* a2   = (const float*)d_in[5];
    const float* b2   = (const float*)d_in[6];
    const float* bias = (const float*)d_in[7];
    float* out = (float*)d_out;

    k_main<<<NBLK, 256>>>(x, W, adj, a1, b1, a2, b2, bias, out);
}